// round 12
// baseline (speedup 1.0000x reference)
#include <cuda_runtime.h>
#include <math.h>

#define TPB   512
#define NWARP 16
#define TCC   8            // channels per tile (all layers)
#define NJL   (3 * TCC)    // 24 gather rows per tile
#define GTILE (NJL * 128)  // 3072 floats per G buffer

typedef unsigned long long ull;

// ---------------- transposed-weight scratch (prep kernels fill these) -------
// Layout: Wt[(c*3 + k)*COUT + o] = W[(o*CIN + c)*3 + k]
__device__ __align__(16) float g_Wt1[128 * 3 * 256];
__device__ __align__(16) float g_Wt2[256 * 3 * 128];
__device__ __align__(16) float g_Wt3[128 * 3 * 64];

// ---------------- f32x2 helpers ---------------------------------------------
__device__ __forceinline__ ull fma2(ull a, ull b, ull c) {
    ull d;
    asm("fma.rn.f32x2 %0, %1, %2, %3;" : "=l"(d) : "l"(a), "l"(b), "l"(c));
    return d;
}
__device__ __forceinline__ ull dup2(float x) {
    ull d;
    asm("mov.b64 %0, {%1, %1};" : "=l"(d) : "f"(x));
    return d;
}
__device__ __forceinline__ float2 unpack2(ull v) {
    float2 r;
    asm("mov.b64 {%0, %1}, %2;" : "=f"(r.x), "=f"(r.y) : "l"(v));
    return r;
}
__device__ __forceinline__ float wredsum(float v) {
#pragma unroll
    for (int o = 16; o; o >>= 1) v += __shfl_xor_sync(0xffffffffu, v, o);
    return v;
}
__device__ __forceinline__ float wredmax(float v) {
#pragma unroll
    for (int o = 16; o; o >>= 1) v = fmaxf(v, __shfl_xor_sync(0xffffffffu, v, o));
    return v;
}

// ---------------- weight transpose prep -------------------------------------
template <int CIN, int COUT>
__device__ __forceinline__ void prep_body(const float* __restrict__ W, float* __restrict__ Wt) {
    int i = blockIdx.x * blockDim.x + threadIdx.x;
    if (i < CIN * 3 * COUT) {
        int o  = i % COUT;
        int ck = i / COUT;
        int k  = ck % 3;
        int c  = ck / 3;
        Wt[i] = W[(o * CIN + c) * 3 + k];
    }
}
__global__ void prep1(const float* __restrict__ W) { prep_body<128, 256>(W, g_Wt1); }
__global__ void prep2(const float* __restrict__ W) { prep_body<256, 128>(W, g_Wt2); }
__global__ void prep3(const float* __restrict__ W) { prep_body<128, 64 >(W, g_Wt3); }

// ---------------- per-thread gather contexts (loop-invariant) ----------------
// 768 gather tasks (jl in [0,24), 32 m-quads) over 512 threads -> 2 contexts.
// ctx0: task tid (jl 0..15, all threads); ctx1: task tid+512 (jl 16..23, tid<256).
struct GCX {
    int4 id;    // node indices for the 4 m's (m=127 slot -> idx 0)
    int  c7;    // channel-in-tile * 128
    int  goff;  // jl*128 + mq*4
};

// ---------------- gather one c-tile into G (LN+leaky folded in) -------------
template <bool XF>
__device__ __forceinline__ void gather_t(const float* __restrict__ sIn,
                                         float* __restrict__ G,
                                         const GCX& g0, const GCX& g1,
                                         int cb7, int tid, float mean, float inv) {
    {
        const float* row = sIn + cb7 + g0.c7;
        float v0 = row[g0.id.x], v1 = row[g0.id.y];
        float v2 = row[g0.id.z], v3 = row[g0.id.w];
        if (XF) {
            v0 = (v0 - mean) * inv; v0 = fmaxf(v0, 0.01f * v0);
            v1 = (v1 - mean) * inv; v1 = fmaxf(v1, 0.01f * v1);
            v2 = (v2 - mean) * inv; v2 = fmaxf(v2, 0.01f * v2);
            v3 = (v3 - mean) * inv; v3 = fmaxf(v3, 0.01f * v3);
        }
        *(float4*)(G + g0.goff) = make_float4(v0, v1, v2, v3);
    }
    if (tid < 256) {
        const float* row = sIn + cb7 + g1.c7;
        float v0 = row[g1.id.x], v1 = row[g1.id.y];
        float v2 = row[g1.id.z], v3 = row[g1.id.w];
        if (XF) {
            v0 = (v0 - mean) * inv; v0 = fmaxf(v0, 0.01f * v0);
            v1 = (v1 - mean) * inv; v1 = fmaxf(v1, 0.01f * v1);
            v2 = (v2 - mean) * inv; v2 = fmaxf(v2, 0.01f * v2);
            v3 = (v3 - mean) * inv; v3 = fmaxf(v3, 0.01f * v3);
        }
        *(float4*)(G + g1.goff) = make_float4(v0, v1, v2, v3);
    }
}

// ---------------- stage one weight tile into SMEM (coalesced) ----------------
// tile t covers rows (t*3*TCC .. ) of Wt; NJL*COUT floats per tile.
template <int COUT>
__device__ __forceinline__ void stage_w(const float* __restrict__ Wt,
                                        float* __restrict__ WS, int t, int tid) {
    constexpr int N4 = NJL * COUT / 4;
    const float4* src = ((const float4*)Wt) + (size_t)t * N4;
#pragma unroll
    for (int i = tid; i < N4; i += TPB)
        ((float4*)WS)[i] = src[i];
}

// ---------------- GEMM accumulate over one tile (G + W from SMEM) ------------
template <int COUT, int OW>
__device__ __forceinline__ void accum(const float* __restrict__ G,
                                      const float* __restrict__ WS,
                                      int Obase, int m0, ull (&acc)[OW / 2][4]) {
#pragma unroll 4
    for (int jl = 0; jl < NJL; jl++) {
        float4 g = *(const float4*)(G + (jl << 7) + m0);
        ull gd0 = dup2(g.x), gd1 = dup2(g.y), gd2 = dup2(g.z), gd3 = dup2(g.w);
        const ulonglong2* wp = (const ulonglong2*)(WS + jl * COUT + Obase);
#pragma unroll
        for (int jj = 0; jj < OW / 4; jj++) {
            ulonglong2 wv = wp[jj];
            acc[2*jj][0] = fma2(wv.x, gd0, acc[2*jj][0]);
            acc[2*jj][1] = fma2(wv.x, gd1, acc[2*jj][1]);
            acc[2*jj][2] = fma2(wv.x, gd2, acc[2*jj][2]);
            acc[2*jj][3] = fma2(wv.x, gd3, acc[2*jj][3]);
            acc[2*jj+1][0] = fma2(wv.y, gd0, acc[2*jj+1][0]);
            acc[2*jj+1][1] = fma2(wv.y, gd1, acc[2*jj+1][1]);
            acc[2*jj+1][2] = fma2(wv.y, gd2, acc[2*jj+1][2]);
            acc[2*jj+1][3] = fma2(wv.y, gd3, acc[2*jj+1][3]);
        }
    }
}

// ---------------- pipelined sweep: stage W+G for t+1 while computing t -------
template <int CIN, int COUT, int OW, bool XF>
__device__ __forceinline__ void conv_sweep(const float* __restrict__ sIn,
                                           const float* __restrict__ Wt,
                                           float* __restrict__ G0, float* __restrict__ G1,
                                           float* __restrict__ W0, float* __restrict__ W1,
                                           const GCX& g0, const GCX& g1,
                                           int Obase, int m0, int tid,
                                           float xm, float xi, ull (&acc)[OW / 2][4]) {
    constexpr int NT = CIN / TCC;
    stage_w<COUT>(Wt, W0, 0, tid);
    gather_t<XF>(sIn, G0, g0, g1, 0, tid, xm, xi);
#pragma unroll 1
    for (int t = 0; t < NT; t++) {
        __syncthreads();
        if (t + 1 < NT) {
            stage_w<COUT>(Wt, (t & 1) ? W0 : W1, t + 1, tid);
            gather_t<XF>(sIn, (t & 1) ? G0 : G1, g0, g1, ((t + 1) * TCC) << 7,
                         tid, xm, xi);
        }
        accum<COUT, OW>((t & 1) ? G1 : G0, (t & 1) ? W1 : W0, Obase, m0, acc);
    }
    __syncthreads();
}

// ---------------- LN stats finalize ------------------------------------------
__device__ __forceinline__ void ln_stats(float ls1, float ls2,
                                         float* __restrict__ RED, float* __restrict__ STAT,
                                         int tid, int w, int lane, float n) {
    float r1 = wredsum(ls1), r2 = wredsum(ls2);
    if (lane == 0) { RED[w] = r1; RED[NWARP + w] = r2; }
    __syncthreads();
    if (tid == 0) {
        float s1 = 0.f, s2 = 0.f;
#pragma unroll
        for (int i = 0; i < NWARP; i++) { s1 += RED[i]; s2 += RED[NWARP + i]; }
        float mean = s1 / n;
        float var  = fmaxf((s2 - s1 * mean) / (n - 1.0f), 0.f);
        STAT[0] = mean;
        STAT[1] = 1.0f / (sqrtf(var) + 1e-5f);
    }
    __syncthreads();
}

// ---------------- fused per-tree kernel --------------------------------------
// Static smem: S1 32768 + S0 16384 + IDXT 384 + RED 32 + POOL 64 + STAT 2.
// G/W tile buffers OVERLAY the dead activation buffer of each layer:
//   L1 mainloop: S1 dead (written only in epilogue)  -> buffers in S1
//   L2 mainloop: S0 dead (input consumed)            -> buffers in S0
//   L3 mainloop: S1 dead                             -> buffers in S1
#define SMEM_FLOATS (32768 + 16384 + 384 + 2 * NWARP + 64 + 2)
#define SMEM_BYTES  (SMEM_FLOATS * 4)

__global__ void __launch_bounds__(TPB, 1) bao_kernel(
    const float* __restrict__ trees, const int* __restrict__ indexes,
    const float* __restrict__ b1, const float* __restrict__ b2,
    const float* __restrict__ b3,
    const float* __restrict__ W4, const float* __restrict__ b4,
    const float* __restrict__ W5, const float* __restrict__ b5,
    float* __restrict__ out) {
    extern __shared__ float sm[];
    float* S1   = sm;                       // 256x128 L1-out (pre-LN)
    float* S0   = sm + 32768;               // 128x128 trees / L2-out / L3-in
    int*   IDXT = (int*)(sm + 49152);       // 3 x 128
    float* RED  = (float*)(IDXT + 384);
    float* POOL = RED + 2 * NWARP;
    float* STAT = POOL + 64;

    const int tid = threadIdx.x, w = tid >> 5, lane = tid & 31;
    const int b = blockIdx.x;
    const int m0 = lane << 2;

    // stage tree + transposed indexes
    {
        const float4* tin = (const float4*)(trees + (size_t)b * 16384);
        float4* s0v = (float4*)S0;
        for (int i = tid; i < 4096; i += TPB) s0v[i] = tin[i];
        const int* ip = indexes + (size_t)b * 381;
        if (tid < 384) {
            int k = tid >> 7, m = tid & 127;
            IDXT[tid] = (m < 127) ? ip[3 * m + k] : 0;
        }
    }
    __syncthreads();

    // build the two per-thread gather contexts (constant for the whole tree)
    GCX g0, g1;
    {
        int e = tid;                         // ctx0: jl 0..15
        int jl = e >> 5, mq = e & 31;
        int c = jl / 3, k = jl - 3 * c;
        g0.c7 = c << 7;
        g0.goff = (jl << 7) + (mq << 2);
        g0.id = *(const int4*)(IDXT + (k << 7) + (mq << 2));

        e = tid + TPB;                       // ctx1: jl 16..23 (tid<256)
        jl = e >> 5; mq = e & 31;
        c = jl / 3; k = jl - 3 * c;
        g1.c7 = c << 7;
        g1.goff = (jl << 7) + (mq << 2);
        g1.id = (jl < NJL) ? *(const int4*)(IDXT + (k << 7) + (mq << 2))
                           : make_int4(0, 0, 0, 0);
    }

    // ================= Layer 1: CIN=128 COUT=256, OW=16, NT=16 ===============
    {
        float* W0b = S1;            float* W1b = S1 + 6144;    // 24*256 each
        float* G0b = S1 + 12288;    float* G1b = S1 + 15360;   // 3072 each
        const int Obase = w * 16;
        ull acc[8][4];
#pragma unroll
        for (int j = 0; j < 8; j++)
#pragma unroll
            for (int mi = 0; mi < 4; mi++) acc[j][mi] = 0ull;
        conv_sweep<128, 256, 16, false>(S0, g_Wt1, G0b, G1b, W0b, W1b, g0, g1,
                                        Obase, m0, tid, 0.f, 1.f, acc);
        float ls1 = 0.f, ls2 = 0.f;
#pragma unroll
        for (int j = 0; j < 8; j++) {
            int o0 = Obase + 2 * j;
            float bb0 = b1[o0], bb1 = b1[o0 + 1];
#pragma unroll
            for (int mi = 0; mi < 4; mi++) {
                int m = m0 + mi;
                if (m < 127) {
                    float2 v = unpack2(acc[j][mi]);
                    float x0 = v.x + bb0, x1 = v.y + bb1;
                    S1[o0 * 128 + m + 1]       = x0;
                    S1[(o0 + 1) * 128 + m + 1] = x1;
                    ls1 += x0 + x1;
                    ls2 += x0 * x0 + x1 * x1;
                }
            }
        }
        if (tid < 256) S1[tid * 128] = 0.f;   // zero node column
        ln_stats(ls1, ls2, RED, STAT, tid, w, lane, 256.f * 128.f);
    }
    float m1 = STAT[0], i1 = STAT[1];

    // ================= Layer 2: CIN=256 COUT=128, OW=8, NT=32 ================
    {
        float* W0b = S0;            float* W1b = S0 + 3072;    // 24*128 each
        float* G0b = S0 + 6144;     float* G1b = S0 + 9216;
        const int Obase = w * 8;
        ull acc[4][4];
#pragma unroll
        for (int j = 0; j < 4; j++)
#pragma unroll
            for (int mi = 0; mi < 4; mi++) acc[j][mi] = 0ull;
        conv_sweep<256, 128, 8, true>(S1, g_Wt2, G0b, G1b, W0b, W1b, g0, g1,
                                      Obase, m0, tid, m1, i1, acc);
        float ls1 = 0.f, ls2 = 0.f;
#pragma unroll
        for (int j = 0; j < 4; j++) {
            int o0 = Obase + 2 * j;
            float bb0 = b2[o0], bb1 = b2[o0 + 1];
#pragma unroll
            for (int mi = 0; mi < 4; mi++) {
                int m = m0 + mi;
                if (m < 127) {
                    float2 v = unpack2(acc[j][mi]);
                    float x0 = v.x + bb0, x1 = v.y + bb1;
                    S0[o0 * 128 + m + 1]       = x0;
                    S0[(o0 + 1) * 128 + m + 1] = x1;
                    ls1 += x0 + x1;
                    ls2 += x0 * x0 + x1 * x1;
                }
            }
        }
        if (tid < 128) S0[tid * 128] = 0.f;
        ln_stats(ls1, ls2, RED, STAT, tid, w, lane, 128.f * 128.f);
    }
    float m2 = STAT[0], i2 = STAT[1];

    // ================= Layer 3: CIN=128 COUT=64, OW=4, NT=16, pool ===========
    {
        float* W0b = S1;            float* W1b = S1 + 1536;    // 24*64 each
        float* G0b = S1 + 3072;     float* G1b = S1 + 6144;
        const int Obase = w * 4;
        ull acc[2][4];
#pragma unroll
        for (int j = 0; j < 2; j++)
#pragma unroll
            for (int mi = 0; mi < 4; mi++) acc[j][mi] = 0ull;
        conv_sweep<128, 64, 4, true>(S0, g_Wt3, G0b, G1b, W0b, W1b, g0, g1,
                                     Obase, m0, tid, m2, i2, acc);
        float ls1 = 0.f, ls2 = 0.f;
        float omax[4];
#pragma unroll
        for (int j = 0; j < 2; j++) {
            int o0 = Obase + 2 * j;
            float bb0 = b3[o0], bb1 = b3[o0 + 1];
            float t0 = -3.4e38f, t1 = -3.4e38f;
#pragma unroll
            for (int mi = 0; mi < 4; mi++) {
                if (m0 + mi < 127) {
                    float2 v = unpack2(acc[j][mi]);
                    float x0 = v.x + bb0, x1 = v.y + bb1;
                    ls1 += x0 + x1;
                    ls2 += x0 * x0 + x1 * x1;
                    t0 = fmaxf(t0, x0);
                    t1 = fmaxf(t1, x1);
                }
            }
            omax[2 * j] = t0; omax[2 * j + 1] = t1;
        }
#pragma unroll
        for (int j = 0; j < 4; j++) {
            float mx = wredmax(omax[j]);
            if (lane == 0) POOL[Obase + j] = fmaxf(mx, 0.f);  // zero node joins max
        }
        ln_stats(ls1, ls2, RED, STAT, tid, w, lane, 64.f * 128.f);
    }

    // ================= head ==================================================
    if (w == 0) {
        float mean = STAT[0], inv = STAT[1];
        float hv = b4[lane];
#pragma unroll 8
        for (int c = 0; c < 64; c++)
            hv += (POOL[c] - mean) * inv * W4[lane * 64 + c];
        hv = hv > 0.f ? hv : 0.01f * hv;
        float val = wredsum(hv * W5[lane]);
        if (lane == 0) out[b] = val + b5[0];
    }
}

extern "C" void kernel_launch(void* const* d_in, const int* in_sizes, int n_in,
                              void* d_out, int out_size) {
    const float* trees = nullptr; const int* indexes = nullptr;
    const float *W1 = nullptr, *b1 = nullptr, *W2 = nullptr, *b2 = nullptr;
    const float *W3 = nullptr, *b3 = nullptr, *W4 = nullptr, *b4 = nullptr;
    const float *W5 = nullptr, *b5 = nullptr;

    for (int i = 0; i < n_in; i++) {
        int s = in_sizes[i];
        const void* p = d_in[i];
        switch (s) {
            case 33554432: trees   = (const float*)p; break;
            case 780288:   indexes = (const int*)p;   break;
            case 98304:    if (!W1) W1 = (const float*)p; else W2 = (const float*)p; break;
            case 256:      b1 = (const float*)p; break;
            case 128:      b2 = (const float*)p; break;
            case 24576:    W3 = (const float*)p; break;
            case 64:       b3 = (const float*)p; break;
            case 2048:     W4 = (const float*)p; break;
            case 32:       if (!b4) b4 = (const float*)p; else W5 = (const float*)p; break;
            case 1:        b5 = (const float*)p; break;
            default: break;
        }
    }

    prep1<<<(128 * 3 * 256 + 255) / 256, 256>>>(W1);
    prep2<<<(256 * 3 * 128 + 255) / 256, 256>>>(W2);
    prep3<<<(128 * 3 * 64  + 255) / 256, 256>>>(W3);

    cudaFuncSetAttribute(bao_kernel, cudaFuncAttributeMaxDynamicSharedMemorySize, SMEM_BYTES);
    bao_kernel<<<2048, TPB, SMEM_BYTES>>>(trees, indexes, b1, b2, b3, W4, b4, W5, b5,
                                          (float*)d_out);
}

// round 17
// speedup vs baseline: 1.4059x; 1.4059x over previous
#include <cuda_runtime.h>
#include <cuda_bf16.h>
#include <cstdint>
#include <math.h>

#define TPB   512
#define NWARP 16

// ---------------- smem float-index layout ------------------------------------
#define S1_F   0            // 256x128 fp32 (L1 out / L2 in), 32768 floats
#define S0_F   32768        // 128x128 fp32 (trees / L2 out / L3 in+out)
#define CTRL   49152
#define IDXT_F CTRL         // int[384]
#define RED_F  (CTRL + 384) // float[32]
#define POOL_F (CTRL + 416) // float[64]
#define STAT_F (CTRL + 480) // float[2]
#define SMEM_FLOATS (CTRL + 482)
#define SMEM_BYTES  (SMEM_FLOATS * 4)

// G tile: k-tile = 32 (2 kchunks of 16). Per m-row: 16 words + 2 pad = 18.
#define ROWW  18
#define GHALF 9216          // bytes per half (128*18*4)
#define GBUF  18432         // hi+lo per buffer
// G double-buffers overlay the DEAD activation region of each layer:
#define L1_G  0             // S1 dead during L1 mainloop
#define L2_G  131072        // S0 dead during L2 mainloop
#define L3_G  0             // S1 dead during L3 mainloop

// ---------------- A-fragment blobs (register-order, hi+lo) -------------------
// word idx = (((t2*OT + ot)*2 + h)*32 + lane)*4 + aid ; t2 = kchunk (16 k)
__device__ __align__(16) uint32_t g_A1[98304];   // L1: 24 kchunks x 16 ot
__device__ __align__(16) uint32_t g_A2[98304];   // L2: 48 x 8
__device__ __align__(16) uint32_t g_A3[24576];   // L3: 24 x 4

// ---------------- helpers ----------------------------------------------------
__device__ __forceinline__ float wredsum(float v) {
#pragma unroll
    for (int o = 16; o; o >>= 1) v += __shfl_xor_sync(0xffffffffu, v, o);
    return v;
}
__device__ __forceinline__ void mma16816(float* d, uint4 a, uint2 b) {
    asm volatile(
        "mma.sync.aligned.m16n8k16.row.col.f32.bf16.bf16.f32 "
        "{%0,%1,%2,%3}, {%4,%5,%6,%7}, {%8,%9}, {%0,%1,%2,%3};"
        : "+f"(d[0]), "+f"(d[1]), "+f"(d[2]), "+f"(d[3])
        : "r"(a.x), "r"(a.y), "r"(a.z), "r"(a.w), "r"(b.x), "r"(b.y));
}

// ---------------- A-fragment prep: split + register-order pack ---------------
template <int CIN, int COUT>
__global__ void prepA(const float* __restrict__ W, uint32_t* __restrict__ out) {
    constexpr int OT = COUT / 16;
    constexpr int NWRD = (3 * CIN / 16) * OT * 2 * 128;
    int i = blockIdx.x * blockDim.x + threadIdx.x;
    if (i >= NWRD) return;
    int aid = i & 3, lane = (i >> 2) & 31, h = (i >> 7) & 1;
    int rest = i >> 8;
    int ot = rest % OT, t2 = rest / OT;
    int g = lane >> 2, tg = lane & 3;
    int o  = ot * 16 + g + (aid & 1) * 8;
    int kl = tg * 2 + ((aid >> 1) & 1) * 8;
    int j0 = t2 * 16 + kl, j1 = j0 + 1;
    int c0 = j0 / 3, k0 = j0 - 3 * c0;
    int c1 = j1 / 3, k1 = j1 - 3 * c1;
    float v0 = W[(o * CIN + c0) * 3 + k0];
    float v1 = W[(o * CIN + c1) * 3 + k1];
    __nv_bfloat16 b0 = __float2bfloat16(v0), b1 = __float2bfloat16(v1);
    if (h) {
        b0 = __float2bfloat16(v0 - __bfloat162float(b0));
        b1 = __float2bfloat16(v1 - __bfloat162float(b1));
    }
    out[i] = (uint32_t)__bfloat16_as_ushort(b0)
           | ((uint32_t)__bfloat16_as_ushort(b1) << 16);
}

// ---------------- gather one k32 tile into G (LN+leaky + bf16 split) ---------
// Thread: m = tid>>2, kc = (tid&3)>>1, p0 = (tid&1)*4 -> 8 consecutive j's.
template <bool XF>
__device__ __forceinline__ void gather_t(const float* __restrict__ actIn,
                                         char* __restrict__ Gb,
                                         int t, int m, int kc, int p0,
                                         int i0, int i1, int i2,
                                         float xm, float xi) {
    int jb = t * 32 + kc * 16 + p0 * 2;
    int c = jb / 3, r = jb - 3 * c;
    unsigned short hh[8], hl[8];
#pragma unroll
    for (int jj = 0; jj < 8; jj++) {
        int node = (r == 0) ? i0 : ((r == 1) ? i1 : i2);
        float v = actIn[(c << 7) + node];
        if (XF) { v = (v - xm) * xi; v = fmaxf(v, 0.01f * v); }
        __nv_bfloat16 hb = __float2bfloat16(v);
        hh[jj] = __bfloat16_as_ushort(hb);
        hl[jj] = __bfloat16_as_ushort(__float2bfloat16(v - __bfloat162float(hb)));
        if (++r == 3) { r = 0; c++; }
    }
    uint32_t* gw = (uint32_t*)(Gb) + m * ROWW + kc * 8 + (p0 ? 1 : 0);
    uint32_t* gl = (uint32_t*)(Gb + GHALF) + m * ROWW + kc * 8 + (p0 ? 1 : 0);
#pragma unroll
    for (int u = 0; u < 4; u++) {
        gw[2 * u] = (uint32_t)hh[2 * u] | ((uint32_t)hh[2 * u + 1] << 16);
        gl[2 * u] = (uint32_t)hl[2 * u] | ((uint32_t)hl[2 * u + 1] << 16);
    }
}

// ---------------- mma over one k32 tile --------------------------------------
template <int OT, int NTW>
__device__ __forceinline__ void mma_tile(const uint32_t* __restrict__ gA,
                                         const char* __restrict__ Gb,
                                         int t, int ot, int nbase,
                                         int g, int tg, float (&acc)[NTW][4]) {
#pragma unroll
    for (int kc = 0; kc < 2; kc++) {
        const uint4* Ap = (const uint4*)gA + ((2 * t + kc) * OT + ot) * 64;
        uint4 ahi = Ap[g * 4 + tg];            // = lane
        uint4 alo = Ap[32 + g * 4 + tg];
#pragma unroll
        for (int nt = 0; nt < NTW; nt++) {
            int m = (nbase + nt) * 8 + g;
            const char* bp = Gb + 4 * (m * ROWW + kc * 8 + tg * 2);
            uint2 bh = *(const uint2*)bp;
            uint2 bl = *(const uint2*)(bp + GHALF);
            mma16816(acc[nt], ahi, bh);
            mma16816(acc[nt], ahi, bl);
            mma16816(acc[nt], alo, bh);
        }
    }
}

// ---------------- pipelined sweep --------------------------------------------
template <int CIN, int OT, int NTW, bool XF>
__device__ __forceinline__ void conv_sweep(const float* __restrict__ actIn,
                                           const uint32_t* __restrict__ gA,
                                           char* __restrict__ smc, int Goff,
                                           int ot, int nbase,
                                           int m, int kc, int p0,
                                           int i0, int i1, int i2,
                                           int g, int tg,
                                           float xm, float xi,
                                           float (&acc)[NTW][4]) {
    constexpr int NT = 3 * CIN / 32;
    gather_t<XF>(actIn, smc + Goff, 0, m, kc, p0, i0, i1, i2, xm, xi);
#pragma unroll 1
    for (int t = 0; t < NT; t++) {
        __syncthreads();
        if (t + 1 < NT)
            gather_t<XF>(actIn, smc + Goff + ((t + 1) & 1) * GBUF,
                         t + 1, m, kc, p0, i0, i1, i2, xm, xi);
        mma_tile<OT, NTW>(gA, smc + Goff + (t & 1) * GBUF, t, ot, nbase, g, tg, acc);
    }
    __syncthreads();
}

// ---------------- LN stats finalize ------------------------------------------
__device__ __forceinline__ void ln_stats(float ls1, float ls2, float* sm,
                                         int tid, int w, int lane, float n) {
    float* RED  = sm + RED_F;
    float* STAT = sm + STAT_F;
    float r1 = wredsum(ls1), r2 = wredsum(ls2);
    if (lane == 0) { RED[w] = r1; RED[NWARP + w] = r2; }
    __syncthreads();
    if (tid == 0) {
        float s1 = 0.f, s2 = 0.f;
#pragma unroll
        for (int i = 0; i < NWARP; i++) { s1 += RED[i]; s2 += RED[NWARP + i]; }
        float mean = s1 / n;
        float var  = fmaxf((s2 - s1 * mean) / (n - 1.0f), 0.f);
        STAT[0] = mean;
        STAT[1] = 1.0f / (sqrtf(var) + 1e-5f);
    }
    __syncthreads();
}

// ---------------- epilogue: bias + store + stats partials --------------------
template <int NTW>
__device__ __forceinline__ void epi_store(float (&acc)[NTW][4],
                                          const float* __restrict__ bias,
                                          float* __restrict__ S,
                                          int obase, int nbase, int g, int tg,
                                          float& ls1, float& ls2) {
    float bb0 = bias[obase + g], bb1 = bias[obase + g + 8];
    float* r0 = S + ((obase + g) << 7);
    float* r1 = S + ((obase + g + 8) << 7);
#pragma unroll
    for (int nt = 0; nt < NTW; nt++) {
        int m0 = (nbase + nt) * 8 + 2 * tg;
        float x0 = acc[nt][0] + bb0, x2 = acc[nt][2] + bb1;
        r0[m0 + 1] = x0; r1[m0 + 1] = x2;
        ls1 += x0 + x2; ls2 += x0 * x0 + x2 * x2;
        if (m0 + 1 < 127) {
            float x1 = acc[nt][1] + bb0, x3 = acc[nt][3] + bb1;
            r0[m0 + 2] = x1; r1[m0 + 2] = x3;
            ls1 += x1 + x3; ls2 += x1 * x1 + x3 * x3;
        }
    }
}

// ---------------- fused per-tree kernel --------------------------------------
__global__ void __launch_bounds__(TPB, 1) bao_kernel(
    const float* __restrict__ trees, const int* __restrict__ indexes,
    const float* __restrict__ b1, const float* __restrict__ b2,
    const float* __restrict__ b3,
    const float* __restrict__ W4, const float* __restrict__ b4,
    const float* __restrict__ W5, const float* __restrict__ b5,
    float* __restrict__ out) {
    extern __shared__ float sm[];
    char*  smc  = (char*)sm;
    float* S1   = sm + S1_F;
    float* S0   = sm + S0_F;
    int*   IDXT = (int*)(sm + IDXT_F);
    float* POOL = sm + POOL_F;
    float* STAT = sm + STAT_F;

    const int tid = threadIdx.x, w = tid >> 5, lane = tid & 31;
    const int g = lane >> 2, tg = lane & 3;
    const int b = blockIdx.x;

    // stage tree + transposed indexes
    {
        const float4* tin = (const float4*)(trees + (size_t)b * 16384);
        float4* s0v = (float4*)S0;
        for (int i = tid; i < 4096; i += TPB) s0v[i] = tin[i];
        const int* ip = indexes + (size_t)b * 381;
        if (tid < 384) {
            int k = tid >> 7, mm = tid & 127;
            IDXT[tid] = (mm < 127) ? ip[3 * mm + k] : 0;
        }
    }
    __syncthreads();

    // per-thread gather context (constant for the whole tree)
    const int gm = tid >> 2;                 // gather row m (0..127)
    const int gkc = (tid & 3) >> 1;          // kchunk within tile
    const int gp0 = (tid & 1) * 4;           // pair base
    const int i0 = IDXT[gm], i1 = IDXT[128 + gm], i2 = IDXT[256 + gm];

    // ================= Layer 1: COUT=256, OT=16 (ot=w), NTW=16 ===============
    {
        float acc[16][4];
#pragma unroll
        for (int nt = 0; nt < 16; nt++)
#pragma unroll
            for (int q = 0; q < 4; q++) acc[nt][q] = 0.f;
        conv_sweep<128, 16, 16, false>(S0, g_A1, smc, L1_G, w, 0,
                                       gm, gkc, gp0, i0, i1, i2, g, tg,
                                       0.f, 1.f, acc);
        float ls1 = 0.f, ls2 = 0.f;
        epi_store<16>(acc, b1, S1, w * 16, 0, g, tg, ls1, ls2);
        if (tid < 256) S1[tid << 7] = 0.f;   // zero node column
        ln_stats(ls1, ls2, sm, tid, w, lane, 256.f * 128.f);
    }
    float m1 = STAT[0], iv1 = STAT[1];

    // ================= Layer 2: COUT=128, OT=8 (ot=w&7), NTW=8 ===============
    {
        float acc[8][4];
#pragma unroll
        for (int nt = 0; nt < 8; nt++)
#pragma unroll
            for (int q = 0; q < 4; q++) acc[nt][q] = 0.f;
        const int ot = w & 7, nbase = (w >> 3) * 8;
        conv_sweep<256, 8, 8, true>(S1, g_A2, smc, L2_G, ot, nbase,
                                    gm, gkc, gp0, i0, i1, i2, g, tg,
                                    m1, iv1, acc);
        float ls1 = 0.f, ls2 = 0.f;
        epi_store<8>(acc, b2, S0, ot * 16, nbase, g, tg, ls1, ls2);
        if (tid < 128) S0[tid << 7] = 0.f;
        ln_stats(ls1, ls2, sm, tid, w, lane, 128.f * 128.f);
    }
    float m2 = STAT[0], iv2 = STAT[1];

    // ================= Layer 3: COUT=64, OT=4 (ot=w&3), NTW=4, pool ==========
    {
        float acc[4][4];
#pragma unroll
        for (int nt = 0; nt < 4; nt++)
#pragma unroll
            for (int q = 0; q < 4; q++) acc[nt][q] = 0.f;
        const int ot = w & 3, nbase = (w >> 2) * 4;
        conv_sweep<128, 4, 4, true>(S0, g_A3, smc, L3_G, ot, nbase,
                                    gm, gkc, gp0, i0, i1, i2, g, tg,
                                    m2, iv2, acc);
        float ls1 = 0.f, ls2 = 0.f;
        epi_store<4>(acc, b3, S0, ot * 16, nbase, g, tg, ls1, ls2);
        if (tid < 64) S0[tid << 7] = 0.f;
        ln_stats(ls1, ls2, sm, tid, w, lane, 64.f * 128.f);
        // pool: max over nodes 0..127 of pre-LN values (monotone LN later)
        if (tid < 64) {
            const float* row = S0 + (tid << 7);
            float mx = 0.f;                  // node 0 = 0
#pragma unroll 4
            for (int n = 1; n < 128; n++) mx = fmaxf(mx, row[n]);
            POOL[tid] = mx;
        }
        __syncthreads();
    }

    // ================= head ==================================================
    if (w == 0) {
        float mean = STAT[0], inv = STAT[1];
        float hv = b4[lane];
#pragma unroll 8
        for (int c = 0; c < 64; c++)
            hv += (POOL[c] - mean) * inv * W4[lane * 64 + c];
        hv = hv > 0.f ? hv : 0.01f * hv;
        float val = wredsum(hv * W5[lane]);
        if (lane == 0) out[b] = val + b5[0];
    }
}

extern "C" void kernel_launch(void* const* d_in, const int* in_sizes, int n_in,
                              void* d_out, int out_size) {
    const float* trees = nullptr; const int* indexes = nullptr;
    const float *W1 = nullptr, *b1 = nullptr, *W2 = nullptr, *b2 = nullptr;
    const float *W3 = nullptr, *b3 = nullptr, *W4 = nullptr, *b4 = nullptr;
    const float *W5 = nullptr, *b5 = nullptr;

    for (int i = 0; i < n_in; i++) {
        int s = in_sizes[i];
        const void* p = d_in[i];
        switch (s) {
            case 33554432: trees   = (const float*)p; break;
            case 780288:   indexes = (const int*)p;   break;
            case 98304:    if (!W1) W1 = (const float*)p; else W2 = (const float*)p; break;
            case 256:      b1 = (const float*)p; break;
            case 128:      b2 = (const float*)p; break;
            case 24576:    W3 = (const float*)p; break;
            case 64:       b3 = (const float*)p; break;
            case 2048:     W4 = (const float*)p; break;
            case 32:       if (!b4) b4 = (const float*)p; else W5 = (const float*)p; break;
            case 1:        b5 = (const float*)p; break;
            default: break;
        }
    }

    uint32_t *dA1, *dA2, *dA3;
    cudaGetSymbolAddress((void**)&dA1, g_A1);
    cudaGetSymbolAddress((void**)&dA2, g_A2);
    cudaGetSymbolAddress((void**)&dA3, g_A3);

    prepA<128, 256><<<(98304 + 255) / 256, 256>>>(W1, dA1);
    prepA<256, 128><<<(98304 + 255) / 256, 256>>>(W2, dA2);
    prepA<128, 64><<<(24576 + 255) / 256, 256>>>(W3, dA3);

    cudaFuncSetAttribute(bao_kernel, cudaFuncAttributeMaxDynamicSharedMemorySize, SMEM_BYTES);
    bao_kernel<<<2048, TPB, SMEM_BYTES>>>(trees, indexes, b1, b2, b3, W4, b4, W5, b5,
                                          (float*)d_out);
}